// round 1
// baseline (speedup 1.0000x reference)
#include <cuda_runtime.h>

// Problem constants
#define BB   2
#define CC   256
#define NN   2304     // 48*48
#define OC3  768
#define NH   8
#define HD   32

// Scratch (device globals: allocation-free per harness rules)
__device__ float g_Y [BB * NN * OC3];       // qkv output, [b][n][768] (o contiguous)
__device__ float g_Kt[BB * CC * NN];        // K transposed, [b][h*32+d][n]
__device__ float g_O [BB * NN * CC];        // attention out, [b][n][c]

// ---------- packed f32x2 helpers (sm_100+ PTX) ----------
__device__ __forceinline__ unsigned long long pack2(float x, float y) {
    unsigned long long r;
    asm("mov.b64 %0, {%1, %2};" : "=l"(r) : "f"(x), "f"(y));
    return r;
}
__device__ __forceinline__ void unpack2(unsigned long long v, float& x, float& y) {
    asm("mov.b64 {%0, %1}, %2;" : "=f"(x), "=f"(y) : "l"(v));
}
__device__ __forceinline__ void fma2(unsigned long long& d, unsigned long long a, unsigned long long b) {
    asm("fma.rn.f32x2 %0, %1, %2, %3;" : "=l"(d) : "l"(a), "l"(b), "l"(d));
}
__device__ __forceinline__ unsigned long long mul2(unsigned long long a, unsigned long long b) {
    unsigned long long r;
    asm("mul.rn.f32x2 %0, %1, %2;" : "=l"(r) : "l"(a), "l"(b));
    return r;
}

// =====================================================================
// Kernel 1: QKV 1x1 conv as GEMM.
//   Y[b][n][o] = sum_c W[o][c] * X[b][c][n] + bias[o]
//   Also writes K portion (o in [256,512)) transposed to g_Kt[b][o-256][n].
// Tiles: 64n x 64o, K-chunk 16, 256 threads, 4x4 microtile per thread.
// =====================================================================
__global__ __launch_bounds__(256) void qkv_kernel(
    const float* __restrict__ X, const float* __restrict__ W,
    const float* __restrict__ bias)
{
    __shared__ float As[16][64];  // W^T tile: [c][o]
    __shared__ float Bs[16][64];  // X tile:   [c][n]

    const int b  = blockIdx.z;
    const int n0 = blockIdx.x * 64;
    const int o0 = blockIdx.y * 64;
    const int t  = threadIdx.x;
    const int tx = t & 15, ty = t >> 4;

    const float* Xb = X + (size_t)b * CC * NN;

    const int wo = t >> 2,  wc = (t & 3) << 2;   // W loader: o row, c col4
    const int xc = t >> 4,  xn = (t & 15) << 2;  // X loader: c row, n col4

    unsigned long long cacc[4][2];
    #pragma unroll
    for (int i = 0; i < 4; i++) { cacc[i][0] = 0ULL; cacc[i][1] = 0ULL; }

    for (int c0 = 0; c0 < CC; c0 += 16) {
        float4 w4 = *(const float4*)(W + (size_t)(o0 + wo) * CC + c0 + wc);
        As[wc + 0][wo] = w4.x; As[wc + 1][wo] = w4.y;
        As[wc + 2][wo] = w4.z; As[wc + 3][wo] = w4.w;
        *(float4*)&Bs[xc][xn] = *(const float4*)(Xb + (size_t)(c0 + xc) * NN + n0 + xn);
        __syncthreads();

        #pragma unroll
        for (int kk = 0; kk < 16; kk++) {
            float4 a4 = *(const float4*)&Bs[kk][ty << 2];              // n side (broadcast)
            ulonglong2 b2 = *(const ulonglong2*)&As[kk][tx << 2];      // o side pairs
            float a[4] = {a4.x, a4.y, a4.z, a4.w};
            #pragma unroll
            for (int i = 0; i < 4; i++) {
                unsigned long long ad = pack2(a[i], a[i]);
                fma2(cacc[i][0], ad, b2.x);
                fma2(cacc[i][1], ad, b2.y);
            }
        }
        __syncthreads();
    }

    float4 bi4 = *(const float4*)(bias + o0 + (tx << 2));
    const int obase = o0 + (tx << 2);
    const bool isK = (obase >= CC) && (obase < 2 * CC);

    #pragma unroll
    for (int i = 0; i < 4; i++) {
        const int n = n0 + (ty << 2) + i;
        float r0, r1, r2, r3;
        unpack2(cacc[i][0], r0, r1);
        unpack2(cacc[i][1], r2, r3);
        float4 r;
        r.x = r0 + bi4.x; r.y = r1 + bi4.y; r.z = r2 + bi4.z; r.w = r3 + bi4.w;
        *(float4*)(g_Y + ((size_t)b * NN + n) * OC3 + obase) = r;
        if (isK) {
            float rv[4] = {r.x, r.y, r.z, r.w};
            #pragma unroll
            for (int j = 0; j < 4; j++) {
                const int hd = obase + j - CC;      // h*32 + d
                g_Kt[((size_t)b * CC + hd) * NN + n] = rv[j];
            }
        }
    }
}

// =====================================================================
// Kernel 2: flash attention per (b, h, q-tile).
//   One CTA: 64 query rows, loop over 36 key tiles of 64.
//   S microtile 4x4 per thread (ty->q rows, tx->k cols), f32x2 packed.
//   O microtile 4 rows x 2 d-cols per thread (tx->d), f32x2 packed.
// =====================================================================
__global__ __launch_bounds__(256) void attn_kernel()
{
    __shared__ float Qs [64][32];   // [q][d]
    __shared__ float Kts[32][64];   // [d][k]  (conflict-free S reads)
    __shared__ float Vs [64][32];   // [m][d]
    __shared__ float Ps [64][64];   // [q][m]

    const int bh = blockIdx.y;
    const int b  = bh >> 3, h = bh & 7;
    const int q0 = blockIdx.x * 64;
    const int t  = threadIdx.x;
    const int tx = t & 15, ty = t >> 4;

    const float* Yb  = g_Y  + (size_t)b * NN * OC3;
    const float* Ktb = g_Kt + ((size_t)b * CC + h * HD) * NN;

    // Load Q tile (64 x 32)
    {
        const int r = t >> 2, c = (t & 3) << 3;
        const float* src = Yb + (size_t)(q0 + r) * OC3 + h * HD + c;
        *(float4*)&Qs[r][c]     = *(const float4*)src;
        *(float4*)&Qs[r][c + 4] = *(const float4*)(src + 4);
    }

    float m_i[4], l_i[4];
    unsigned long long o2[4];
    #pragma unroll
    for (int i = 0; i < 4; i++) { m_i[i] = -1e30f; l_i[i] = 0.0f; o2[i] = 0ULL; }

    const float scale = 0.17677669529663689f;  // 1/sqrt(32)

    #pragma unroll 1
    for (int kt = 0; kt < 36; kt++) {
        const int k0 = kt * 64;
        __syncthreads();  // previous PV done reading Vs/Ps
        {
            const int r = t >> 3, c = (t & 7) << 3;               // K: 32 x 64
            const float* ks = Ktb + (size_t)r * NN + k0 + c;
            *(float4*)&Kts[r][c]     = *(const float4*)ks;
            *(float4*)&Kts[r][c + 4] = *(const float4*)(ks + 4);
            const int r2 = t >> 2, cc = (t & 3) << 3;             // V: 64 x 32
            const float* vs = Yb + (size_t)(k0 + r2) * OC3 + 2 * CC + h * HD + cc;
            *(float4*)&Vs[r2][cc]     = *(const float4*)vs;
            *(float4*)&Vs[r2][cc + 4] = *(const float4*)(vs + 4);
        }
        __syncthreads();

        // S = Q K^T  (pairs along k columns)
        unsigned long long sAcc[4][2];
        #pragma unroll
        for (int i = 0; i < 4; i++) { sAcc[i][0] = 0ULL; sAcc[i][1] = 0ULL; }

        #pragma unroll
        for (int d4 = 0; d4 < 32; d4 += 4) {
            float a[4][4];
            #pragma unroll
            for (int i = 0; i < 4; i++) {
                float4 a4 = *(const float4*)&Qs[(ty << 2) + i][d4];
                a[i][0] = a4.x; a[i][1] = a4.y; a[i][2] = a4.z; a[i][3] = a4.w;
            }
            #pragma unroll
            for (int u = 0; u < 4; u++) {
                ulonglong2 bb = *(const ulonglong2*)&Kts[d4 + u][tx << 2];
                #pragma unroll
                for (int i = 0; i < 4; i++) {
                    unsigned long long ad = pack2(a[i][u], a[i][u]);
                    fma2(sAcc[i][0], ad, bb.x);
                    fma2(sAcc[i][1], ad, bb.y);
                }
            }
        }

        // Online softmax per q row (row = 16 lanes of a half-warp)
        #pragma unroll
        for (int i = 0; i < 4; i++) {
            float s0, s1, s2, s3;
            unpack2(sAcc[i][0], s0, s1);
            unpack2(sAcc[i][1], s2, s3);
            s0 *= scale; s1 *= scale; s2 *= scale; s3 *= scale;
            float mx = fmaxf(fmaxf(s0, s1), fmaxf(s2, s3));
            #pragma unroll
            for (int msk = 8; msk >= 1; msk >>= 1)
                mx = fmaxf(mx, __shfl_xor_sync(0xffffffffu, mx, msk));
            const float mnew = fmaxf(m_i[i], mx);
            const float p0 = __expf(s0 - mnew), p1 = __expf(s1 - mnew);
            const float p2 = __expf(s2 - mnew), p3 = __expf(s3 - mnew);
            float rs = (p0 + p1) + (p2 + p3);
            #pragma unroll
            for (int msk = 8; msk >= 1; msk >>= 1)
                rs += __shfl_xor_sync(0xffffffffu, rs, msk);
            const float alpha = __expf(m_i[i] - mnew);
            l_i[i] = l_i[i] * alpha + rs;
            m_i[i] = mnew;
            o2[i]  = mul2(o2[i], pack2(alpha, alpha));
            *(float2*)&Ps[(ty << 2) + i][(tx << 2)]     = make_float2(p0, p1);
            *(float2*)&Ps[(ty << 2) + i][(tx << 2) + 2] = make_float2(p2, p3);
        }
        __syncthreads();

        // O += P V  (pairs along d)
        #pragma unroll
        for (int m4 = 0; m4 < 64; m4 += 4) {
            float p[4][4];
            #pragma unroll
            for (int i = 0; i < 4; i++) {
                float4 p4 = *(const float4*)&Ps[(ty << 2) + i][m4];
                p[i][0] = p4.x; p[i][1] = p4.y; p[i][2] = p4.z; p[i][3] = p4.w;
            }
            #pragma unroll
            for (int u = 0; u < 4; u++) {
                unsigned long long v2 = *(const unsigned long long*)&Vs[m4 + u][tx << 1];
                #pragma unroll
                for (int i = 0; i < 4; i++)
                    fma2(o2[i], pack2(p[i][u], p[i][u]), v2);
            }
        }
    }

    // Finalize: O /= l, write [b][n][c] with c = h*32 + d
    #pragma unroll
    for (int i = 0; i < 4; i++) {
        const float inv = 1.0f / l_i[i];
        float x0, x1;
        unpack2(o2[i], x0, x1);
        const int n = q0 + (ty << 2) + i;
        *(float2*)(g_O + ((size_t)b * NN + n) * CC + h * HD + (tx << 1))
            = make_float2(x0 * inv, x1 * inv);
    }
}

// =====================================================================
// Kernel 3: proj 1x1 conv + bias + residual.
//   out[b][c][n] = sum_c' Wp[c][c'] * O[b][n][c'] + bp[c] + x[b][c][n]
// =====================================================================
__global__ __launch_bounds__(256) void proj_kernel(
    const float* __restrict__ X, const float* __restrict__ Wp,
    const float* __restrict__ bp, float* __restrict__ out)
{
    __shared__ float As[16][64];  // Wp^T tile: [c'][c]
    __shared__ float Bs[16][64];  // O^T tile:  [c'][n]

    const int b  = blockIdx.z;
    const int n0 = blockIdx.x * 64;
    const int c0 = blockIdx.y * 64;
    const int t  = threadIdx.x;
    const int tx = t & 15, ty = t >> 4;

    const float* Ob = g_O + (size_t)b * NN * CC;
    const int wr = t >> 2, wc = (t & 3) << 2;

    unsigned long long cacc[4][2];
    #pragma unroll
    for (int i = 0; i < 4; i++) { cacc[i][0] = 0ULL; cacc[i][1] = 0ULL; }

    for (int p0 = 0; p0 < CC; p0 += 16) {
        float4 w4 = *(const float4*)(Wp + (size_t)(c0 + wr) * CC + p0 + wc);
        As[wc + 0][wr] = w4.x; As[wc + 1][wr] = w4.y;
        As[wc + 2][wr] = w4.z; As[wc + 3][wr] = w4.w;
        float4 o4 = *(const float4*)(Ob + (size_t)(n0 + wr) * CC + p0 + wc);
        Bs[wc + 0][wr] = o4.x; Bs[wc + 1][wr] = o4.y;
        Bs[wc + 2][wr] = o4.z; Bs[wc + 3][wr] = o4.w;
        __syncthreads();

        #pragma unroll
        for (int kk = 0; kk < 16; kk++) {
            float4 a4 = *(const float4*)&As[kk][ty << 2];           // c side (broadcast)
            ulonglong2 b2 = *(const ulonglong2*)&Bs[kk][tx << 2];   // n side pairs
            float a[4] = {a4.x, a4.y, a4.z, a4.w};
            #pragma unroll
            for (int i = 0; i < 4; i++) {
                unsigned long long ad = pack2(a[i], a[i]);
                fma2(cacc[i][0], ad, b2.x);
                fma2(cacc[i][1], ad, b2.y);
            }
        }
        __syncthreads();
    }

    const float* Xb = X + (size_t)b * CC * NN;
    #pragma unroll
    for (int i = 0; i < 4; i++) {
        const int c = c0 + (ty << 2) + i;
        const float bi = bp[c];
        float4 x4 = *(const float4*)(Xb + (size_t)c * NN + n0 + (tx << 2));
        float r0, r1, r2, r3;
        unpack2(cacc[i][0], r0, r1);
        unpack2(cacc[i][1], r2, r3);
        float4 r;
        r.x = r0 + bi + x4.x; r.y = r1 + bi + x4.y;
        r.z = r2 + bi + x4.z; r.w = r3 + bi + x4.w;
        *(float4*)(out + (size_t)b * CC * NN + (size_t)c * NN + n0 + (tx << 2)) = r;
    }
}

// =====================================================================
extern "C" void kernel_launch(void* const* d_in, const int* in_sizes, int n_in,
                              void* d_out, int out_size)
{
    const float* x      = (const float*)d_in[0];
    const float* w_qkv  = (const float*)d_in[1];
    const float* b_qkv  = (const float*)d_in[2];
    const float* w_proj = (const float*)d_in[3];
    const float* b_proj = (const float*)d_in[4];
    float* out = (float*)d_out;

    qkv_kernel <<<dim3(NN / 64, OC3 / 64, BB), 256>>>(x, w_qkv, b_qkv);
    attn_kernel<<<dim3(NN / 64, BB * NH, 1), 256>>>();
    proj_kernel<<<dim3(NN / 64, CC / 64, BB), 256>>>(x, w_proj, b_proj, out);
}